// round 5
// baseline (speedup 1.0000x reference)
#include <cuda_runtime.h>
#include <cuda_bf16.h>
#include <cuda_pipeline_primitives.h>
#include <math.h>

// Problem: b=2, f=8, c=64, h=w=256  (fp32)
//   k_sum[bf,c] = sum_{hw} nbr[bf,c,hw]
//   out[bf,hw]  = sigmoid( sum_c ref[bf,c,hw] * k_sum[bf,c] )
// HBM streaming: 2 x 268MB reads + 4MB write.

#define BF     16          // b*f
#define C      64
#define HW     65536       // 256*256
#define HW4    16384       // HW / 4 (float4 units)
#define STAGES 4           // cp.async pipeline depth (8KB per stage)

__device__ float g_ksum[BF * C];

// ---------------------------------------------------------------------------
// Kernel 1: per-channel-plane reduction. One block per (bf,c) plane (256 KB
// contiguous). ~6.86 TB/s measured — leave untouched.
// ---------------------------------------------------------------------------
__global__ __launch_bounds__(256) void ksum_kernel(const float* __restrict__ nbr) {
    const int ch = blockIdx.x;                       // 0..1023 == bf*64 + c
    const float4* __restrict__ p =
        reinterpret_cast<const float4*>(nbr + (size_t)ch * HW);

    float s = 0.0f;
    #pragma unroll 8
    for (int i = threadIdx.x; i < HW4; i += 256) {
        float4 v = __ldcs(p + i);
        s += (v.x + v.y) + (v.z + v.w);
    }

    #pragma unroll
    for (int off = 16; off > 0; off >>= 1)
        s += __shfl_xor_sync(0xffffffffu, s, off);

    __shared__ float warp_sums[8];
    const int lane = threadIdx.x & 31;
    const int wid  = threadIdx.x >> 5;
    if (lane == 0) warp_sums[wid] = s;
    __syncthreads();

    if (wid == 0) {
        float t = (lane < 8) ? warp_sums[lane] : 0.0f;
        #pragma unroll
        for (int off = 4; off > 0; off >>= 1)
            t += __shfl_xor_sync(0xffffffffu, t, off);
        if (lane == 0) g_ksum[ch] = t;
    }
}

// ---------------------------------------------------------------------------
// Kernel 2: weighted channel contraction + sigmoid, cp.async pipelined.
// 512 blocks x 256 threads; block owns an 8KB pixel window. Per channel step,
// 8KB streams G->SMEM via LDGSTS (register-pressure-free => deterministic
// 4-stage x 8KB MLP). Each thread consumes its OWN async copies, so the main
// loop has no block-level syncs — only __pipeline_wait_prior.
// ---------------------------------------------------------------------------
__global__ __launch_bounds__(256) void weight_kernel(const float* __restrict__ ref,
                                                     float* __restrict__ out) {
    const int bf  = blockIdx.x >> 5;                     // 32 blocks per bf
    const int win = (blockIdx.x & 31) << 9;              // window base (float4)
    const int t   = threadIdx.x;

    __shared__ float4 buf[STAGES][512];
    __shared__ float  sk[C];
    if (t < C) sk[t] = g_ksum[bf * C + t];
    __syncthreads();

    const float4* __restrict__ base =
        reinterpret_cast<const float4*>(ref) + (size_t)bf * C * HW4 + win;

    // Prologue: stages 0..STAGES-2 in flight.
    #pragma unroll
    for (int s = 0; s < STAGES - 1; s++) {
        const float4* src = base + (size_t)s * HW4;
        __pipeline_memcpy_async(&buf[s][t],       src + t,       16);
        __pipeline_memcpy_async(&buf[s][t + 256], src + t + 256, 16);
        __pipeline_commit();
    }

    float a0x = 0.f, a0y = 0.f, a0z = 0.f, a0w = 0.f;
    float a1x = 0.f, a1y = 0.f, a1z = 0.f, a1w = 0.f;

    #pragma unroll 4
    for (int c = 0; c < C; c++) {
        const int pc = c + (STAGES - 1);
        if (pc < C) {
            const int ps = pc & (STAGES - 1);
            const float4* src = base + (size_t)pc * HW4;
            __pipeline_memcpy_async(&buf[ps][t],       src + t,       16);
            __pipeline_memcpy_async(&buf[ps][t + 256], src + t + 256, 16);
        }
        __pipeline_commit();                       // keep group count aligned
        __pipeline_wait_prior(STAGES - 1);         // stage c complete (own copies)

        const int s = c & (STAGES - 1);
        float4 v0 = buf[s][t];
        float4 v1 = buf[s][t + 256];
        const float k = sk[c];
        a0x = fmaf(v0.x, k, a0x);
        a0y = fmaf(v0.y, k, a0y);
        a0z = fmaf(v0.z, k, a0z);
        a0w = fmaf(v0.w, k, a0w);
        a1x = fmaf(v1.x, k, a1x);
        a1y = fmaf(v1.y, k, a1y);
        a1z = fmaf(v1.z, k, a1z);
        a1w = fmaf(v1.w, k, a1w);
    }

    float4 r0, r1;
    r0.x = 1.0f / (1.0f + expf(-a0x));
    r0.y = 1.0f / (1.0f + expf(-a0y));
    r0.z = 1.0f / (1.0f + expf(-a0z));
    r0.w = 1.0f / (1.0f + expf(-a0w));
    r1.x = 1.0f / (1.0f + expf(-a1x));
    r1.y = 1.0f / (1.0f + expf(-a1y));
    r1.z = 1.0f / (1.0f + expf(-a1z));
    r1.w = 1.0f / (1.0f + expf(-a1w));

    float4* o = reinterpret_cast<float4*>(out) + (size_t)bf * HW4 + win;
    o[t]       = r0;
    o[t + 256] = r1;
}

// ---------------------------------------------------------------------------
extern "C" void kernel_launch(void* const* d_in, const int* in_sizes, int n_in,
                              void* d_out, int out_size) {
    const float* nbr = (const float*)d_in[0];
    const float* ref = (const float*)d_in[1];
    float* out = (float*)d_out;

    ksum_kernel<<<BF * C, 256>>>(nbr);
    weight_kernel<<<BF * HW4 / 512, 256>>>(ref, out);
}

// round 6
// speedup vs baseline: 1.0142x; 1.0142x over previous
#include <cuda_runtime.h>
#include <cuda_bf16.h>
#include <math.h>

// Problem: b=2, f=8, c=64, h=w=256  (fp32)
//   k_sum[bf,c] = sum_{hw} nbr[bf,c,hw]
//   out[bf,hw]  = sigmoid( sum_c ref[bf,c,hw] * k_sum[bf,c] )
// HBM streaming: 2 x 268MB reads + 4MB write.
// Measured: ksum ~6.76 TB/s, weight pinned ~6.0-6.1 TB/s across 4 load
// mechanisms -> attack the non-load parts (store policy, epilogue).

#define BF     16          // b*f
#define C      64
#define HW     65536       // 256*256
#define HW4    16384       // HW / 4 (float4 units)

__device__ float g_ksum[BF * C];

// ---------------------------------------------------------------------------
// Kernel 1: per-channel-plane reduction. One block per (bf,c) plane (256 KB
// contiguous). ~6.76 TB/s measured — unchanged.
// ---------------------------------------------------------------------------
__global__ __launch_bounds__(256) void ksum_kernel(const float* __restrict__ nbr) {
    const int ch = blockIdx.x;                       // 0..1023 == bf*64 + c
    const float4* __restrict__ p =
        reinterpret_cast<const float4*>(nbr + (size_t)ch * HW);

    float s = 0.0f;
    #pragma unroll 8
    for (int i = threadIdx.x; i < HW4; i += 256) {
        float4 v = __ldcs(p + i);
        s += (v.x + v.y) + (v.z + v.w);
    }

    #pragma unroll
    for (int off = 16; off > 0; off >>= 1)
        s += __shfl_xor_sync(0xffffffffu, s, off);

    __shared__ float warp_sums[8];
    const int lane = threadIdx.x & 31;
    const int wid  = threadIdx.x >> 5;
    if (lane == 0) warp_sums[wid] = s;
    __syncthreads();

    if (wid == 0) {
        float t = (lane < 8) ? warp_sums[lane] : 0.0f;
        #pragma unroll
        for (int off = 4; off > 0; off >>= 1)
            t += __shfl_xor_sync(0xffffffffu, t, off);
        if (lane == 0) g_ksum[ch] = t;
    }
}

// ---------------------------------------------------------------------------
// Kernel 2: weighted channel contraction + sigmoid (R2 shape: best measured).
// 512 blocks x 256 threads, 2 float4/thread, 8 KB contiguous per channel step.
// New: streaming stores (__stcs) so output never dirties L2, and fast-math
// sigmoid (__expf + __fdividef) to shrink the per-block epilogue tail.
// ---------------------------------------------------------------------------
__global__ __launch_bounds__(256) void weight_kernel(const float* __restrict__ ref,
                                                     float* __restrict__ out) {
    const int bf  = blockIdx.x >> 5;                     // 32 blocks per bf
    const int win = (blockIdx.x & 31) << 9;              // window base (float4)
    const int p0  = win + threadIdx.x;
    const int p1  = p0 + 256;

    __shared__ float sk[C];
    if (threadIdx.x < C) sk[threadIdx.x] = g_ksum[bf * C + threadIdx.x];
    __syncthreads();

    const float4* __restrict__ base =
        reinterpret_cast<const float4*>(ref) + (size_t)bf * C * HW4;

    float a0x = 0.f, a0y = 0.f, a0z = 0.f, a0w = 0.f;
    float a1x = 0.f, a1y = 0.f, a1z = 0.f, a1w = 0.f;

    #pragma unroll
    for (int c = 0; c < C; c++) {
        const float4* chp = base + (size_t)c * HW4;
        float4 v0 = __ldcs(chp + p0);
        float4 v1 = __ldcs(chp + p1);
        float  k  = sk[c];
        a0x = fmaf(v0.x, k, a0x);
        a0y = fmaf(v0.y, k, a0y);
        a0z = fmaf(v0.z, k, a0z);
        a0w = fmaf(v0.w, k, a0w);
        a1x = fmaf(v1.x, k, a1x);
        a1y = fmaf(v1.y, k, a1y);
        a1z = fmaf(v1.z, k, a1z);
        a1w = fmaf(v1.w, k, a1w);
    }

    float4 r0, r1;
    r0.x = __fdividef(1.0f, 1.0f + __expf(-a0x));
    r0.y = __fdividef(1.0f, 1.0f + __expf(-a0y));
    r0.z = __fdividef(1.0f, 1.0f + __expf(-a0z));
    r0.w = __fdividef(1.0f, 1.0f + __expf(-a0w));
    r1.x = __fdividef(1.0f, 1.0f + __expf(-a1x));
    r1.y = __fdividef(1.0f, 1.0f + __expf(-a1y));
    r1.z = __fdividef(1.0f, 1.0f + __expf(-a1z));
    r1.w = __fdividef(1.0f, 1.0f + __expf(-a1w));

    float4* o = reinterpret_cast<float4*>(out) + (size_t)bf * HW4;
    __stcs(o + p0, r0);   // evict-first streaming store
    __stcs(o + p1, r1);
}

// ---------------------------------------------------------------------------
extern "C" void kernel_launch(void* const* d_in, const int* in_sizes, int n_in,
                              void* d_out, int out_size) {
    const float* nbr = (const float*)d_in[0];
    const float* ref = (const float*)d_in[1];
    float* out = (float*)d_out;

    ksum_kernel<<<BF * C, 256>>>(nbr);
    weight_kernel<<<BF * HW4 / 512, 256>>>(ref, out);
}